// round 9
// baseline (speedup 1.0000x reference)
#include <cuda_runtime.h>
#include <math.h>

#define HH 2048
#define WW 2048
#define NF 64
#define MAXD 12
#define NSLOT 8191            // heap-ordered tree, depths 0..12
#define PW 128                // warp patch width  (32 lanes x 4 px)
#define PH 4                  // warp patch height (rows per thread)

// Node encoding (self-looping leaves, branchless descent):
//   bits [11:0]  split coordinate (interior) or 4095 sentinel (leaf)
//   bits [24:12] child base index (interior: 2j+1; leaf: j -> self-loop)
//   bit  [25]    axis (1 = vertical/x split)  -- 0 on leaves
//   bits [31:26] color index (leaf only)
__device__ int g_tree[NSLOT];

// ---------------------------------------------------------------------------
// Kernel 1: build explicit tree. Thread j walks root -> heap slot j with a
// branchless walk. Argmax: 4 threads/row, float4 loads, 2-shfl merge.
// ---------------------------------------------------------------------------
__global__ __launch_bounds__(512) void k_tree(
    const float* __restrict__ sel,
    const float* __restrict__ ratios)
{
    __shared__ float s_ratio[NF];
    __shared__ int   s_left[NF], s_right[NF];

    const int tid = threadIdx.x;

    {   // ---- argmax: row = tid>>2 (0..127), sub = tid&3 covers 16 elems ----
        const int row   = tid >> 2;
        const int sub   = tid & 3;
        const int frame = row >> 1;
        const int side  = row & 1;
        const float4* p = (const float4*)(sel + frame * 2 * NF + side * NF + sub * 16);

        float4 a = p[0], b = p[1], c = p[2], d = p[3];
        float vals[16] = {a.x,a.y,a.z,a.w, b.x,b.y,b.z,b.w,
                          c.x,c.y,c.z,c.w, d.x,d.y,d.z,d.w};
        float best = vals[0];
        int   bi   = sub * 16;
        #pragma unroll
        for (int k = 1; k < 16; k++)
            if (vals[k] > best) { best = vals[k]; bi = sub * 16 + k; }

        #pragma unroll
        for (int off = 1; off <= 2; off <<= 1) {
            float ov = __shfl_xor_sync(0xffffffffu, best, off);
            int   oi = __shfl_xor_sync(0xffffffffu, bi,   off);
            if (ov > best || (ov == best && oi < bi)) { best = ov; bi = oi; }
        }
        if (sub == 0) { if (side == 0) s_left[frame] = bi; else s_right[frame] = bi; }
    }
    if (tid < NF) s_ratio[tid] = ratios[tid];
    __syncthreads();

    const int j = blockIdx.x * 512 + tid;
    if (j >= NSLOT) return;

    const int depth = 31 - __clz(j + 1);        // 0..12
    int idx = 0, x0 = 0, y0 = 0, w = WW, h = HH;
    bool dead = false;

    for (int k = depth - 1; k >= 0; k--) {
        bool leaf = (w < 2) | (h < 2);
        dead = dead | leaf;
        int  bit  = ((j + 1) >> k) & 1;
        int  vert = idx & 1;
        float rt  = s_ratio[idx];
        int  dim  = vert ? w : h;
        int  cut  = max(1, (int)floorf((float)dim * rt));
        int  ndim = bit ? dim - cut : cut;
        int  oadd = bit ? cut : 0;
        int  nidx = bit ? s_right[idx] : s_left[idx];
        if (!dead) {
            if (vert) { x0 += oadd; w = ndim; }
            else      { y0 += oadd; h = ndim; }
            idx = nidx;
        }
    }
    if (dead) return;                           // unreachable slot (garbage ok)

    if (depth == MAXD || w < 2 || h < 2) {
        g_tree[j] = 4095 | (j << 12) | (idx << 26);             // leaf, self-loop
    } else {
        float rt = s_ratio[idx];
        int s;
        if (idx & 1) s = x0 + max(1, (int)floorf((float)w * rt));
        else         s = y0 + max(1, (int)floorf((float)h * rt));
        g_tree[j] = s | ((2 * j + 1) << 12) | ((idx & 1) << 25);
    }
}

// ---------------------------------------------------------------------------
// Kernel 2: render. Warp = 128x4 patch; thread owns a 4x4 pixel block
// (4 consecutive x, 4 rows). Warp-uniform prefix walk; per-lane branchless
// descents with x-run reuse (xcov = leaf right edge) and full-row reuse
// (ryAll = min leaf bottom across the row). Stores are STG.128 per plane.
// ---------------------------------------------------------------------------
__global__ __launch_bounds__(256) void k_render(
    const float* __restrict__ colors,
    float* __restrict__ out)
{
    __shared__ float4 s_col[NF];
    const int t = threadIdx.y * 32 + threadIdx.x;
    if (t < NF)
        s_col[t] = make_float4(colors[3 * t], colors[3 * t + 1], colors[3 * t + 2], 0.f);
    __syncthreads();

    const int tx0   = blockIdx.x * PW;                   // 0..15 * 128
    const int wy0   = (blockIdx.y * 8 + threadIdx.y) * PH;
    const int xbase = tx0 + threadIdx.x * 4;

    // ---- warp-uniform prefix walk (identical on all lanes) ----
    int pcur = 0, pd = 0;
    int pv = __ldg(&g_tree[0]);
    bool pleaf = false;
    while (true) {
        int s = pv & 0xFFF;
        if (s == 4095) { pleaf = true; break; }          // patch inside one leaf
        if (pv & (1 << 25)) {                            // vertical split
            if      (tx0 + PW <= s) pcur = 2 * pcur + 1;
            else if (tx0 >= s)      pcur = 2 * pcur + 2;
            else break;
        } else {                                         // horizontal split
            if      (wy0 + PH <= s) pcur = 2 * pcur + 1;
            else if (wy0 >= s)      pcur = 2 * pcur + 2;
            else break;
        }
        pd++;
        pv = __ldg(&g_tree[pcur]);
    }

    float4* o0 = (float4*)(out + wy0 * WW + xbase);
    float4* o1 = (float4*)(out + HH * WW + wy0 * WW + xbase);
    float4* o2 = (float4*)(out + 2 * HH * WW + wy0 * WW + xbase);
    const int rs = WW / 4;                               // float4 row stride

    if (pleaf) {                                         // whole-patch fast path
        float4 c = s_col[(unsigned)pv >> 26];
        float4 vr = make_float4(c.x, c.x, c.x, c.x);
        float4 vg = make_float4(c.y, c.y, c.y, c.y);
        float4 vb = make_float4(c.z, c.z, c.z, c.z);
        #pragma unroll
        for (int q = 0; q < PH; q++) {
            o0[q * rs] = vr; o1[q * rs] = vg; o2[q * rs] = vb;
        }
        return;
    }

    const int TR = MAXD - pd;                            // uniform trip count

    float r[4], g[4], b[4];
    int ryAll = -1;                                      // row colors valid while y < ryAll

    #pragma unroll
    for (int q = 0; q < PH; q++) {
        const int y = wy0 + q;
        if (y >= ryAll) {                                // recompute this row
            ryAll = HH;
            int xcov = -1;                               // colors valid while x < xcov
            float4 col = make_float4(0.f, 0.f, 0.f, 0.f);
            #pragma unroll
            for (int k = 0; k < 4; k++) {
                const int xq = xbase + k;
                if (xq >= xcov) {                        // descend at (xq, y)
                    int cur = pcur, v = pv;
                    int rx = WW, ry = HH;
                    for (int it = 0; it < TR; it++) {    // branchless fixed trips
                        int  s     = v & 0xFFF;
                        bool vert  = (v & (1 << 25)) != 0;
                        int  coord = vert ? xq : y;
                        bool go    = coord >= s;
                        if (!go) { if (vert) rx = min(rx, s); else ry = min(ry, s); }
                        cur = ((v >> 12) & 0x1FFF) + (go ? 1 : 0);
                        v = __ldg(&g_tree[cur]);
                    }
                    col = s_col[(unsigned)v >> 26];
                    xcov = rx;
                    ryAll = min(ryAll, ry);
                }
                r[k] = col.x; g[k] = col.y; b[k] = col.z;
            }
        }
        o0[q * rs] = make_float4(r[0], r[1], r[2], r[3]);
        o1[q * rs] = make_float4(g[0], g[1], g[2], g[3]);
        o2[q * rs] = make_float4(b[0], b[1], b[2], b[3]);
    }
}

extern "C" void kernel_launch(void* const* d_in, const int* in_sizes, int n_in,
                              void* d_out, int out_size) {
    const float* colors = (const float*)d_in[0];   // frame_colors    [64, 3]
    const float* sel    = (const float*)d_in[1];   // frame_selection [64, 2, 64]
    const float* ratios = (const float*)d_in[2];   // split_ratios    [64]
    float* out = (float*)d_out;                    // [3, 2048, 2048] fp32

    k_tree<<<16, 512>>>(sel, ratios);

    dim3 block(32, 8);
    dim3 grid(WW / PW, HH / (PH * 8));             // 16 x 64
    k_render<<<grid, block>>>(colors, out);
}

// round 10
// speedup vs baseline: 1.2847x; 1.2847x over previous
#include <cuda_runtime.h>
#include <math.h>

#define HH 2048
#define WW 2048
#define NF 64
#define MAXD 12
#define NSLOT 8191            // heap-ordered tree, depths 0..12

// Word encoding (per node):
//   bits [11:0]  split coordinate (interior) or 4095 sentinel (leaf)
//   bits [24:12] child base (interior: 2j+1) / self index (leaf: j -> self-loop)
//   bit  [25]    axis (1 = vertical/x split), 0 on leaves
//   bits [31:26] color index (leaf only)
// Fat node: g_tree4[j] = { word(j), word(left child), word(right child), 0 }
// -> one LDG.128 decides TWO levels of descent.
__device__ int4 g_tree4[NSLOT];

__device__ __forceinline__ int make_word(int slot, int idx, int x0, int y0,
                                         int w, int h, int depth, const float* sr)
{
    if (depth == MAXD || w < 2 || h < 2)
        return 4095 | (slot << 12) | (idx << 26);            // leaf, self-loop
    int   vert = idx & 1;
    int   dim  = vert ? w : h;
    int   cut  = max(1, (int)floorf((float)dim * sr[idx]));
    int   s    = (vert ? x0 : y0) + cut;
    return s | ((2 * slot + 1) << 12) | (vert << 25);
}

// ---------------------------------------------------------------------------
// Kernel 1: build fat tree. Thread j walks root -> slot j (branchless), then
// emits its own word plus both children's words (derived in-register).
// Argmax: 4 threads/row, float4 loads, 2-shfl merge.
// ---------------------------------------------------------------------------
__global__ __launch_bounds__(512) void k_tree(
    const float* __restrict__ sel,
    const float* __restrict__ ratios)
{
    __shared__ float s_ratio[NF];
    __shared__ int   s_left[NF], s_right[NF];

    const int tid = threadIdx.x;

    {   // ---- argmax: row = tid>>2 (0..127), sub = tid&3 covers 16 elems ----
        const int row   = tid >> 2;
        const int sub   = tid & 3;
        const int frame = row >> 1;
        const int side  = row & 1;
        const float4* p = (const float4*)(sel + frame * 2 * NF + side * NF + sub * 16);

        float4 a = p[0], b = p[1], c = p[2], d = p[3];
        float vals[16] = {a.x,a.y,a.z,a.w, b.x,b.y,b.z,b.w,
                          c.x,c.y,c.z,c.w, d.x,d.y,d.z,d.w};
        float best = vals[0];
        int   bi   = sub * 16;
        #pragma unroll
        for (int k = 1; k < 16; k++)
            if (vals[k] > best) { best = vals[k]; bi = sub * 16 + k; }

        #pragma unroll
        for (int off = 1; off <= 2; off <<= 1) {
            float ov = __shfl_xor_sync(0xffffffffu, best, off);
            int   oi = __shfl_xor_sync(0xffffffffu, bi,   off);
            if (ov > best || (ov == best && oi < bi)) { best = ov; bi = oi; }
        }
        if (sub == 0) { if (side == 0) s_left[frame] = bi; else s_right[frame] = bi; }
    }
    if (tid < NF) s_ratio[tid] = ratios[tid];
    __syncthreads();

    const int j = blockIdx.x * 512 + tid;
    if (j >= NSLOT) return;

    const int depth = 31 - __clz(j + 1);        // 0..12
    int idx = 0, x0 = 0, y0 = 0, w = WW, h = HH;
    bool dead = false;

    for (int k = depth - 1; k >= 0; k--) {
        bool leaf = (w < 2) | (h < 2);
        dead = dead | leaf;
        int  bit  = ((j + 1) >> k) & 1;
        int  vert = idx & 1;
        float rt  = s_ratio[idx];
        int  dim  = vert ? w : h;
        int  cut  = max(1, (int)floorf((float)dim * rt));
        int  ndim = bit ? dim - cut : cut;
        int  oadd = bit ? cut : 0;
        int  nidx = bit ? s_right[idx] : s_left[idx];
        if (!dead) {
            if (vert) { x0 += oadd; w = ndim; }
            else      { y0 += oadd; h = ndim; }
            idx = nidx;
        }
    }
    if (dead) return;                           // unreachable slot, never read

    const bool jleaf = (depth == MAXD) || (w < 2) || (h < 2);
    int wj, wl, wr;
    if (jleaf) {
        wj = 4095 | (j << 12) | (idx << 26);
        wl = wj; wr = wj;                       // self-loop
    } else {
        int   vert = idx & 1;
        int   dim  = vert ? w : h;
        int   cut  = max(1, (int)floorf((float)dim * s_ratio[idx]));
        int   s    = (vert ? x0 : y0) + cut;
        wj = s | ((2 * j + 1) << 12) | (vert << 25);
        int li = s_left[idx], ri = s_right[idx];
        if (vert) {
            wl = make_word(2 * j + 1, li, x0,       y0, cut,     h, depth + 1, s_ratio);
            wr = make_word(2 * j + 2, ri, x0 + cut, y0, w - cut, h, depth + 1, s_ratio);
        } else {
            wl = make_word(2 * j + 1, li, x0, y0,       w, cut,     depth + 1, s_ratio);
            wr = make_word(2 * j + 2, ri, x0, y0 + cut, w, h - cut, depth + 1, s_ratio);
        }
    }
    g_tree4[j] = make_int4(wj, wl, wr, 0);
}

// ---------------------------------------------------------------------------
// Uniform pair-walk for a rect: descends while the split doesn't cross the
// rect; two levels per LDG.128. On exit: cur/word/pd describe the stop node
// (word's split==4095 means the rect lies inside a leaf).
// ---------------------------------------------------------------------------
__device__ __forceinline__ void walk_rect(int& cur, int& word, int& pd,
                                          int rx0, int rxw, int ry0, int ryh)
{
    int4 nd = __ldg(&g_tree4[cur]);
    while (true) {
        int va = nd.x;
        int sA = va & 0xFFF;
        if (sA == 4095) { word = va; break; }               // leaf
        bool vA = (va & (1 << 25)) != 0;
        int  lo = vA ? rx0 : ry0;
        int  hi = lo + (vA ? rxw : ryh);
        int  goA;
        if      (hi <= sA) goA = 0;
        else if (lo >= sA) goA = 1;
        else { word = va; break; }                          // crosses
        int bcur = ((va >> 12) & 0x1FFF) + goA;
        int vb   = goA ? nd.z : nd.y;

        int sB = vb & 0xFFF;
        if (sB == 4095) { cur = bcur; word = vb; pd += 1; break; }
        bool vB = (vb & (1 << 25)) != 0;
        int  lo2 = vB ? rx0 : ry0;
        int  hi2 = lo2 + (vB ? rxw : ryh);
        int  goB;
        if      (hi2 <= sB) goB = 0;
        else if (lo2 >= sB) goB = 1;
        else { cur = bcur; word = vb; pd += 1; break; }     // crosses
        cur = ((vb >> 12) & 0x1FFF) + goB;
        pd += 2;
        nd = __ldg(&g_tree4[cur]);
    }
}

// ---------------------------------------------------------------------------
// Kernel 2: render. Block = 32x32 tile; warp = 32x4 patch; thread = 1 column
// x 4 rows. Warp 0 walks the tree for the whole 32x32 rect (amortizes the
// prefix 8x); each warp extends ~1-2 levels for its patch; per-lane descent
// is branchless with 2 levels per load and row reuse via reachy.
// ---------------------------------------------------------------------------
__global__ __launch_bounds__(256) void k_render(
    const float* __restrict__ colors,
    float* __restrict__ out)
{
    __shared__ float4 s_col[NF];
    __shared__ int    s_b[2];                   // block prefix: cur, pd

    const int t = threadIdx.y * 32 + threadIdx.x;
    if (t < NF)
        s_col[t] = make_float4(colors[3 * t], colors[3 * t + 1], colors[3 * t + 2], 0.f);

    const int tx0 = blockIdx.x * 32;
    const int by0 = blockIdx.y * 32;

    if (threadIdx.y == 0) {                     // warp 0: block-level walk (uniform)
        int cur = 0, word = 0, pd = 0;
        walk_rect(cur, word, pd, tx0, 32, by0, 32);
        if (threadIdx.x == 0) { s_b[0] = cur; s_b[1] = pd; }
    }
    __syncthreads();

    const int wy0 = by0 + threadIdx.y * 4;

    // warp-level extension for the 32x4 patch
    int cur = s_b[0], pd = s_b[1], word = 0;
    walk_rect(cur, word, pd, tx0, 32, wy0, 4);

    const int x    = tx0 + threadIdx.x;
    const int base = wy0 * WW + x;

    if ((word & 0xFFF) == 4095) {               // patch inside one leaf
        float4 c = s_col[(unsigned)word >> 26];
        #pragma unroll
        for (int q = 0; q < 4; q++) {
            out[base + q * WW]               = c.x;
            out[HH * WW + base + q * WW]     = c.y;
            out[2 * HH * WW + base + q * WW] = c.z;
        }
        return;
    }

    const int TR  = MAXD - pd;                  // remaining levels (>=1)
    const int TRP = (TR + 2) >> 1;              // pair iterations; last vb is a leaf word

    float4 col = make_float4(0.f, 0.f, 0.f, 0.f);
    int reachy = -1;

    #pragma unroll
    for (int q = 0; q < 4; q++) {
        const int y = wy0 + q;
        if (y >= reachy) {                      // recompute (warp-convergent trigger)
            int c2 = cur, ry = HH, vb = 0;
            for (int i = 0; i < TRP; i++) {     // branchless, 2 levels per load
                int4 nd = __ldg(&g_tree4[c2]);
                int  va = nd.x;
                int  sA = va & 0xFFF;
                bool vA = (va & (1 << 25)) != 0;
                bool gA = (vA ? x : y) >= sA;
                if (!gA && !vA) ry = min(ry, sA);
                vb = gA ? nd.z : nd.y;
                int  sB = vb & 0xFFF;
                bool vB = (vb & (1 << 25)) != 0;
                bool gB = (vB ? x : y) >= sB;
                if (!gB && !vB) ry = min(ry, sB);
                c2 = ((vb >> 12) & 0x1FFF) + (gB ? 1 : 0);
            }
            col = s_col[(unsigned)vb >> 26];
            reachy = ry;
        }
        out[base + q * WW]               = col.x;
        out[HH * WW + base + q * WW]     = col.y;
        out[2 * HH * WW + base + q * WW] = col.z;
    }
}

extern "C" void kernel_launch(void* const* d_in, const int* in_sizes, int n_in,
                              void* d_out, int out_size) {
    const float* colors = (const float*)d_in[0];   // frame_colors    [64, 3]
    const float* sel    = (const float*)d_in[1];   // frame_selection [64, 2, 64]
    const float* ratios = (const float*)d_in[2];   // split_ratios    [64]
    float* out = (float*)d_out;                    // [3, 2048, 2048] fp32

    k_tree<<<16, 512>>>(sel, ratios);

    dim3 block(32, 8);
    dim3 grid(WW / 32, HH / 32);                   // 64 x 64
    k_render<<<grid, block>>>(colors, out);
}